// round 6
// baseline (speedup 1.0000x reference)
#include <cuda_runtime.h>
#include <math.h>

// Problem dims
#define BB 256
#define TT 512
#define HH 256
#define G3 768          // 3*H
#define INDIM 75
#define BT (BB*TT)      // 131072

// ---------------- scratch (device globals; no allocations allowed) ---------
__device__ float g_xg[(size_t)BB * TT * G3];     // input-gate preactivations (reused per layer)
__device__ float g_out0[(size_t)BB * TT * HH];   // layer-0 hidden states
__device__ float g_hT[BB * HH];                  // layer-1 final hidden state

__device__ __forceinline__ unsigned f2tf32(float v) {
    unsigned u;
    asm("cvt.rna.tf32.f32 %0, %1;" : "=r"(u) : "f"(v));
    return u;
}

__device__ __forceinline__ void mma_tf32(float c[4], const unsigned a[4], unsigned b0, unsigned b1) {
    asm volatile(
        "mma.sync.aligned.m16n8k8.row.col.f32.tf32.tf32.f32 "
        "{%0,%1,%2,%3}, {%4,%5,%6,%7}, {%8,%9}, {%0,%1,%2,%3};"
        : "+f"(c[0]), "+f"(c[1]), "+f"(c[2]), "+f"(c[3])
        : "r"(a[0]), "r"(a[1]), "r"(a[2]), "r"(a[3]), "r"(b0), "r"(b1));
}

__device__ __forceinline__ unsigned smem_u32(const void* p) {
    unsigned a;
    asm("{ .reg .u64 t; cvta.to.shared.u64 t, %1; cvt.u32.u64 %0, t; }" : "=r"(a) : "l"(p));
    return a;
}

__device__ __forceinline__ unsigned mapa_rank(unsigned addr, unsigned rank) {
    unsigned r;
    asm("mapa.shared::cluster.u32 %0, %1, %2;" : "=r"(r) : "r"(addr), "r"(rank));
    return r;
}

#define CLUSTER_SYNC() do {                                            \
    asm volatile("barrier.cluster.arrive.aligned;" ::: "memory");      \
    asm volatile("barrier.cluster.wait.aligned;" ::: "memory");        \
} while (0)

// ---------------- TF32 tensor-core GEMM: C = A[M,K] @ W[N,K]^T + bias ------
#define TBM 128
#define TBN 64
#define TBK 16
#define TPAD 20

__global__ __launch_bounds__(256) void tf32_gemm_bias_kernel(
    const float* __restrict__ A, const float* __restrict__ W,
    const float* __restrict__ bias, float* __restrict__ C,
    int M, int N, int K)
{
    __shared__ unsigned As[TBM * TPAD];
    __shared__ unsigned Bs[TBN * TPAD];

    const int tid = threadIdx.x;
    const int wid = tid >> 5, lane = tid & 31;
    const int g = lane >> 2, t = lane & 3;
    const int wm = wid & 3, wn = wid >> 2;
    const int m0 = blockIdx.y * TBM;
    const int n0 = blockIdx.x * TBN;

    float acc[2][4][4];
#pragma unroll
    for (int mt = 0; mt < 2; mt++)
#pragma unroll
        for (int nt = 0; nt < 4; nt++)
#pragma unroll
            for (int i = 0; i < 4; i++) acc[mt][nt][i] = 0.f;

    const int am = tid >> 4;
    const int ak = tid & 15;
    const int bn = tid >> 2;
    const int bk4 = (tid & 3) * 4;

    float ra[8], rb[4];
    const int nk = (K + TBK - 1) / TBK;

    {
#pragma unroll
        for (int i = 0; i < 8; i++) {
            int m = am + i * 16;
            ra[i] = (ak < K) ? __ldg(&A[(size_t)(m0 + m) * K + ak]) : 0.f;
        }
#pragma unroll
        for (int i = 0; i < 4; i++) {
            int k = bk4 + i;
            rb[i] = (k < K) ? __ldg(&W[(size_t)(n0 + bn) * K + k]) : 0.f;
        }
    }

    for (int kt = 0; kt < nk; kt++) {
#pragma unroll
        for (int i = 0; i < 8; i++) As[(am + i * 16) * TPAD + ak] = f2tf32(ra[i]);
#pragma unroll
        for (int i = 0; i < 4; i++) Bs[bn * TPAD + bk4 + i] = f2tf32(rb[i]);
        __syncthreads();

        if (kt + 1 < nk) {
            const int kb = (kt + 1) * TBK;
#pragma unroll
            for (int i = 0; i < 8; i++) {
                int m = am + i * 16;
                ra[i] = (kb + ak < K) ? __ldg(&A[(size_t)(m0 + m) * K + kb + ak]) : 0.f;
            }
#pragma unroll
            for (int i = 0; i < 4; i++) {
                int k = kb + bk4 + i;
                rb[i] = (k < K) ? __ldg(&W[(size_t)(n0 + bn) * K + k]) : 0.f;
            }
        }

#pragma unroll
        for (int ks = 0; ks < 2; ks++) {
            const int k = ks * 8;
            unsigned af[2][4];
#pragma unroll
            for (int mt = 0; mt < 2; mt++) {
                int row = wm * 32 + mt * 16;
                af[mt][0] = As[(row + g) * TPAD + k + t];
                af[mt][1] = As[(row + g + 8) * TPAD + k + t];
                af[mt][2] = As[(row + g) * TPAD + k + t + 4];
                af[mt][3] = As[(row + g + 8) * TPAD + k + t + 4];
            }
#pragma unroll
            for (int nt = 0; nt < 4; nt++) {
                int col = wn * 32 + nt * 8;
                unsigned b0 = Bs[(col + g) * TPAD + k + t];
                unsigned b1 = Bs[(col + g) * TPAD + k + t + 4];
#pragma unroll
                for (int mt = 0; mt < 2; mt++) mma_tf32(acc[mt][nt], af[mt], b0, b1);
            }
        }
        __syncthreads();
    }

#pragma unroll
    for (int mt = 0; mt < 2; mt++) {
#pragma unroll
        for (int nt = 0; nt < 4; nt++) {
            int row = m0 + wm * 32 + mt * 16 + g;
            int col = n0 + wn * 32 + nt * 8 + 2 * t;
            float b0 = bias[col], b1 = bias[col + 1];
            C[(size_t)row * N + col]           = acc[mt][nt][0] + b0;
            C[(size_t)row * N + col + 1]       = acc[mt][nt][1] + b1;
            C[(size_t)(row + 8) * N + col]     = acc[mt][nt][2] + b0;
            C[(size_t)(row + 8) * N + col + 1] = acc[mt][nt][3] + b1;
        }
    }
}

// ---------------- fp32 GEMM (tiny FC) --------------------------------------
#define GBM 128
#define GBN 64
#define GBK 8
__global__ __launch_bounds__(256) void gemm_bias_kernel(
    const float* __restrict__ A, const float* __restrict__ W,
    const float* __restrict__ bias, float* __restrict__ C,
    int M, int N, int K)
{
    __shared__ float As[GBK][GBM];
    __shared__ float Bs[GBK][GBN + 4];

    int tid = threadIdx.x;
    int tx = tid & 15;
    int ty = tid >> 4;
    int m0 = blockIdx.x * GBM;
    int n0 = blockIdx.y * GBN;

    float acc[8][4];
#pragma unroll
    for (int i = 0; i < 8; i++)
#pragma unroll
        for (int j = 0; j < 4; j++) acc[i][j] = 0.f;

    for (int k0 = 0; k0 < K; k0 += GBK) {
#pragma unroll
        for (int i = 0; i < 4; i++) {
            int idx = tid + i * 256;
            int m = idx >> 3, kk = idx & 7;
            float v = (k0 + kk < K) ? A[(size_t)(m0 + m) * K + k0 + kk] : 0.f;
            As[kk][m] = v;
        }
#pragma unroll
        for (int i = 0; i < 2; i++) {
            int idx = tid + i * 256;
            int n = idx >> 3, kk = idx & 7;
            float v = (k0 + kk < K) ? W[(size_t)(n0 + n) * K + k0 + kk] : 0.f;
            Bs[kk][n] = v;
        }
        __syncthreads();
#pragma unroll
        for (int kk = 0; kk < GBK; kk++) {
            float a[8], b[4];
#pragma unroll
            for (int i = 0; i < 8; i++) a[i] = As[kk][ty * 8 + i];
#pragma unroll
            for (int j = 0; j < 4; j++) b[j] = Bs[kk][tx * 4 + j];
#pragma unroll
            for (int i = 0; i < 8; i++)
#pragma unroll
                for (int j = 0; j < 4; j++) acc[i][j] = fmaf(a[i], b[j], acc[i][j]);
        }
        __syncthreads();
    }

    float bb[4];
#pragma unroll
    for (int j = 0; j < 4; j++) bb[j] = bias[n0 + tx * 4 + j];
#pragma unroll
    for (int i = 0; i < 8; i++) {
        size_t row = (size_t)(m0 + ty * 8 + i) * N + n0 + tx * 4;
#pragma unroll
        for (int j = 0; j < 4; j++) C[row + j] = acc[i][j] + bb[j];
    }
}

// ---------------- dual-stream cluster GRU recurrence -----------------------
// 16 clusters x 8 CTAs; cluster = 16 batches split into 2 streams of 8.
// CTA = 32 units (96 gate rows). W_hh fragments register-resident.
// Iteration: mmaA; mmaB; sync; epiA+pushA; epiB+pushB; cluster.sync.
// Stream A's DSMEM delivery hides under stream B's work and vice versa;
// one latency chain now advances TWO steps of work.
#define CL 8
#define RT_THREADS 192
#define RT_GRID 128
#define HP 260          // h row stride (words): banks 4g+t -> conflict-free
#define DSP2 9          // Ds row stride

__global__ __launch_bounds__(RT_THREADS, 1) __cluster_dims__(CL, 1, 1)
void gru_rec_ds2_kernel(
    const float* __restrict__ W_hh, const float* __restrict__ b_hh, int layer0)
{
    __shared__ unsigned hsA[2][8 * HP];   // stream A h (tf32) [b][unit]
    __shared__ unsigned hsB[2][8 * HP];   // stream B
    __shared__ float    DsA[96 * DSP2];
    __shared__ float    DsB[96 * DSP2];

    const int tid = threadIdx.x;
    const int wid = tid >> 5;             // 0..5
    const int lane = tid & 31;
    const int g = lane >> 2, t = lane & 3;

    unsigned rank;
    asm("mov.u32 %0, %%cluster_ctarank;" : "=r"(rank));
    const int bg = blockIdx.x >> 3;       // batch group 0..15
    const int j0 = (int)rank * 32;
    const int b0 = bg * 16;

    // ---- preload static W_hh fragments into registers ----
    const int gate_w = wid >> 1;
    const int wrow = gate_w * HH + j0 + (wid & 1) * 16;
    unsigned a[32][4];
#pragma unroll
    for (int ks = 0; ks < 32; ks++) {
        int k = ks * 8;
        a[ks][0] = f2tf32(__ldg(&W_hh[(size_t)(wrow + g) * HH + k + t]));
        a[ks][1] = f2tf32(__ldg(&W_hh[(size_t)(wrow + g + 8) * HH + k + t]));
        a[ks][2] = f2tf32(__ldg(&W_hh[(size_t)(wrow + g) * HH + k + t + 4]));
        a[ks][3] = f2tf32(__ldg(&W_hh[(size_t)(wrow + g + 8) * HH + k + t + 4]));
    }

    // ---- epilogue assignment: 128 threads; (eb, ju2) = batch 0..7, unit pair
    const int eb = (tid & 127) >> 4;      // 0..7
    const int ju2 = (tid & 15) * 2;       // unit base 0..30
    float bhr[2], bhz[2], bhn[2];
    if (tid < 128) {
#pragma unroll
        for (int i = 0; i < 2; i++) {
            int j = j0 + ju2 + i;
            bhr[i] = __ldg(&b_hh[j]);
            bhz[i] = __ldg(&b_hh[HH + j]);
            bhn[i] = __ldg(&b_hh[2 * HH + j]);
        }
    }

    // ---- remote destination addresses ----
    unsigned dst[CL];
    unsigned bufDelta, abDelta;
    {
        unsigned lA0 = smem_u32(&hsA[0][eb * HP + j0 + ju2]);
        bufDelta = smem_u32(&hsA[1][eb * HP + j0 + ju2]) - lA0;
        abDelta  = smem_u32(&hsB[0][eb * HP + j0 + ju2]) - lA0;
#pragma unroll
        for (int r = 0; r < CL; r++) dst[r] = mapa_rank(lA0, (unsigned)r);
    }

    // ---- zero-init step-0 buffers ----
    for (int idx = tid; idx < 8 * HP; idx += RT_THREADS) {
        hsA[0][idx] = 0u;
        hsB[0][idx] = 0u;
    }
    __syncthreads();
    CLUSTER_SYNC();

    float hpA[2] = {0.f, 0.f}, hpB[2] = {0.f, 0.f};

    // ---- preload xg for step 0 (both streams) ----
    float2 xrA, xzA, xnA, xrB, xzB, xnB;
    if (tid < 128) {
        const float* xa = &g_xg[((size_t)(b0 + eb) * TT) * G3 + j0 + ju2];
        xrA = *(const float2*)&xa[0];
        xzA = *(const float2*)&xa[HH];
        xnA = *(const float2*)&xa[2 * HH];
        const float* xb = &g_xg[((size_t)(b0 + 8 + eb) * TT) * G3 + j0 + ju2];
        xrB = *(const float2*)&xb[0];
        xzB = *(const float2*)&xb[HH];
        xnB = *(const float2*)&xb[2 * HH];
    }

    for (int s = 0; s < TT; s++) {
        const int cur = s & 1;
        const int nxt = cur ^ 1;

        // ---- prefetch xg for s+1 ----
        float2 xrA_n, xzA_n, xnA_n, xrB_n, xzB_n, xnB_n;
        if (tid < 128 && s + 1 < TT) {
            const float* xa = &g_xg[((size_t)(b0 + eb) * TT + (s + 1)) * G3 + j0 + ju2];
            xrA_n = *(const float2*)&xa[0];
            xzA_n = *(const float2*)&xa[HH];
            xnA_n = *(const float2*)&xa[2 * HH];
            const float* xb = &g_xg[((size_t)(b0 + 8 + eb) * TT + (s + 1)) * G3 + j0 + ju2];
            xrB_n = *(const float2*)&xb[0];
            xzB_n = *(const float2*)&xb[HH];
            xnB_n = *(const float2*)&xb[2 * HH];
        }

        // ---- mma, both streams (8 independent accumulator chains) ----
        const unsigned* hbA = hsA[cur];
        const unsigned* hbB = hsB[cur];
        float cA[4][4], cB[4][4];
#pragma unroll
        for (int c = 0; c < 4; c++)
#pragma unroll
            for (int j = 0; j < 4; j++) { cA[c][j] = 0.f; cB[c][j] = 0.f; }
#pragma unroll
        for (int ks = 0; ks < 32; ks++) {
            int k = ks * 8;
            unsigned a0 = hbA[g * HP + k + t];
            unsigned a1 = hbA[g * HP + k + t + 4];
            unsigned b0v = hbB[g * HP + k + t];
            unsigned b1v = hbB[g * HP + k + t + 4];
            mma_tf32(cA[ks & 3], a[ks], a0, a1);
            mma_tf32(cB[ks & 3], a[ks], b0v, b1v);
        }
#pragma unroll
        for (int j = 0; j < 4; j++) {
            cA[0][j] = (cA[0][j] + cA[1][j]) + (cA[2][j] + cA[3][j]);
            cB[0][j] = (cB[0][j] + cB[1][j]) + (cB[2][j] + cB[3][j]);
        }
        {
            int lr = wid * 16 + g;
            DsA[lr * DSP2 + 2 * t]           = cA[0][0];
            DsA[lr * DSP2 + 2 * t + 1]       = cA[0][1];
            DsA[(lr + 8) * DSP2 + 2 * t]     = cA[0][2];
            DsA[(lr + 8) * DSP2 + 2 * t + 1] = cA[0][3];
            DsB[lr * DSP2 + 2 * t]           = cB[0][0];
            DsB[lr * DSP2 + 2 * t + 1]       = cB[0][1];
            DsB[(lr + 8) * DSP2 + 2 * t]     = cB[0][2];
            DsB[(lr + 8) * DSP2 + 2 * t + 1] = cB[0][3];
        }
        __syncthreads();

        // ---- epilogues + pushes ----
        if (tid < 128) {
            const unsigned bofs = nxt ? bufDelta : 0u;

            // ----- stream A -----
            float hnA[2];
#pragma unroll
            for (int i = 0; i < 2; i++) {
                int jl = ju2 + i;
                float xr = i ? xrA.y : xrA.x;
                float xz = i ? xzA.y : xzA.x;
                float xn = i ? xnA.y : xnA.x;
                float pr = DsA[jl * DSP2 + eb];
                float pz = DsA[(32 + jl) * DSP2 + eb];
                float pn = DsA[(64 + jl) * DSP2 + eb];
                float er = __expf(-(xr + bhr[i] + pr));
                float ez = __expf(-(xz + bhz[i] + pz));
                float r = 1.f / (1.f + er);
                float z = 1.f / (1.f + ez);
                float e2 = __expf(2.f * (xn + r * (bhn[i] + pn)));
                float nn = 1.f - 2.f / (e2 + 1.f);
                hnA[i] = (1.f - z) * nn + z * hpA[i];
                hpA[i] = hnA[i];
            }
            {
                unsigned u0 = f2tf32(hnA[0]), u1 = f2tf32(hnA[1]);
#pragma unroll
                for (int rr = 0; rr < CL; rr++) {
                    int r = (rr + (tid & 7)) & (CL - 1);
                    asm volatile("st.shared::cluster.v2.b32 [%0], {%1,%2};"
                                 :: "r"(dst[r] + bofs), "r"(u0), "r"(u1) : "memory");
                }
            }
            if (layer0)
                *(float2*)&g_out0[((size_t)(b0 + eb) * TT + s) * HH + j0 + ju2] =
                    make_float2(hnA[0], hnA[1]);
            else if (s == TT - 1)
                *(float2*)&g_hT[(size_t)(b0 + eb) * HH + j0 + ju2] =
                    make_float2(hnA[0], hnA[1]);

            // ----- stream B -----
            float hnB[2];
#pragma unroll
            for (int i = 0; i < 2; i++) {
                int jl = ju2 + i;
                float xr = i ? xrB.y : xrB.x;
                float xz = i ? xzB.y : xzB.x;
                float xn = i ? xnB.y : xnB.x;
                float pr = DsB[jl * DSP2 + eb];
                float pz = DsB[(32 + jl) * DSP2 + eb];
                float pn = DsB[(64 + jl) * DSP2 + eb];
                float er = __expf(-(xr + bhr[i] + pr));
                float ez = __expf(-(xz + bhz[i] + pz));
                float r = 1.f / (1.f + er);
                float z = 1.f / (1.f + ez);
                float e2 = __expf(2.f * (xn + r * (bhn[i] + pn)));
                float nn = 1.f - 2.f / (e2 + 1.f);
                hnB[i] = (1.f - z) * nn + z * hpB[i];
                hpB[i] = hnB[i];
            }
            {
                unsigned u0 = f2tf32(hnB[0]), u1 = f2tf32(hnB[1]);
#pragma unroll
                for (int rr = 0; rr < CL; rr++) {
                    int r = (rr + (tid & 7)) & (CL - 1);
                    asm volatile("st.shared::cluster.v2.b32 [%0], {%1,%2};"
                                 :: "r"(dst[r] + bofs + abDelta), "r"(u0), "r"(u1) : "memory");
                }
            }
            if (layer0)
                *(float2*)&g_out0[((size_t)(b0 + 8 + eb) * TT + s) * HH + j0 + ju2] =
                    make_float2(hnB[0], hnB[1]);
            else if (s == TT - 1)
                *(float2*)&g_hT[(size_t)(b0 + 8 + eb) * HH + j0 + ju2] =
                    make_float2(hnB[0], hnB[1]);

            // rotate prefetched xg
            xrA = xrA_n; xzA = xzA_n; xnA = xnA_n;
            xrB = xrB_n; xzB = xzB_n; xnB = xnB_n;
        }

        // ---- one cluster barrier per iteration (orders DSMEM pushes) ----
        CLUSTER_SYNC();
    }
}

// ---------------------------------------------------------------------------
extern "C" void kernel_launch(void* const* d_in, const int* in_sizes, int n_in,
                              void* d_out, int out_size)
{
    const float* x     = (const float*)d_in[0];
    const float* W_ih0 = (const float*)d_in[1];
    const float* W_hh0 = (const float*)d_in[2];
    const float* b_ih0 = (const float*)d_in[3];
    const float* b_hh0 = (const float*)d_in[4];
    const float* W_ih1 = (const float*)d_in[5];
    const float* W_hh1 = (const float*)d_in[6];
    const float* b_ih1 = (const float*)d_in[7];
    const float* b_hh1 = (const float*)d_in[8];
    const float* fc_W  = (const float*)d_in[9];
    const float* fc_b  = (const float*)d_in[10];
    float* out = (float*)d_out;

    float *xg, *out0, *hT;
    cudaGetSymbolAddress((void**)&xg,   g_xg);
    cudaGetSymbolAddress((void**)&out0, g_out0);
    cudaGetSymbolAddress((void**)&hT,   g_hT);

    // layer 0 input preactivations: [BT,75] @ [768,75]^T   (TF32 tensor cores)
    tf32_gemm_bias_kernel<<<dim3(G3 / TBN, BT / TBM), 256>>>(x, W_ih0, b_ih0, xg, BT, G3, INDIM);
    // layer 0 recurrence -> g_out0 (dual-stream cluster)
    gru_rec_ds2_kernel<<<RT_GRID, RT_THREADS>>>(W_hh0, b_hh0, 1);
    // layer 1 input preactivations: [BT,256] @ [768,256]^T (TF32 tensor cores)
    tf32_gemm_bias_kernel<<<dim3(G3 / TBN, BT / TBM), 256>>>(out0, W_ih1, b_ih1, xg, BT, G3, HH);
    // layer 1 recurrence -> g_hT
    gru_rec_ds2_kernel<<<RT_GRID, RT_THREADS>>>(W_hh1, b_hh1, 0);
    // FC: [256,256] @ [256,256]^T + b (fp32, tiny)
    gemm_bias_kernel<<<dim3(BB / GBM, HH / GBN), 256>>>(hT, fc_W, fc_b, out, BB, HH, HH);
}

// round 7
// speedup vs baseline: 1.3203x; 1.3203x over previous
#include <cuda_runtime.h>
#include <math.h>

// Problem dims
#define BB 256
#define TT 512
#define HH 256
#define G3 768          // 3*H
#define INDIM 75
#define BT (BB*TT)      // 131072

// ---------------- scratch (device globals; no allocations allowed) ---------
__device__ float g_xg[(size_t)BB * TT * G3];     // input-gate preactivations (reused per layer)
__device__ float g_out0[(size_t)BB * TT * HH];   // layer-0 hidden states
__device__ float g_hT[BB * HH];                  // layer-1 final hidden state

__device__ __forceinline__ unsigned f2tf32(float v) {
    unsigned u;
    asm("cvt.rna.tf32.f32 %0, %1;" : "=r"(u) : "f"(v));
    return u;
}

__device__ __forceinline__ void mma_tf32(float c[4], const unsigned a[4], unsigned b0, unsigned b1) {
    asm volatile(
        "mma.sync.aligned.m16n8k8.row.col.f32.tf32.tf32.f32 "
        "{%0,%1,%2,%3}, {%4,%5,%6,%7}, {%8,%9}, {%0,%1,%2,%3};"
        : "+f"(c[0]), "+f"(c[1]), "+f"(c[2]), "+f"(c[3])
        : "r"(a[0]), "r"(a[1]), "r"(a[2]), "r"(a[3]), "r"(b0), "r"(b1));
}

__device__ __forceinline__ unsigned smem_u32(const void* p) {
    unsigned a;
    asm("{ .reg .u64 t; cvta.to.shared.u64 t, %1; cvt.u32.u64 %0, t; }" : "=r"(a) : "l"(p));
    return a;
}

#define CLUSTER_SYNC() do {                                            \
    asm volatile("barrier.cluster.arrive.aligned;" ::: "memory");      \
    asm volatile("barrier.cluster.wait.aligned;" ::: "memory");        \
} while (0)

// ================= TF32 GEMM, vector loads (K % 4 == 0, K=256) ============
// C[M,N] = A[M,K] @ W[N,K]^T + bias. BM=128, BN=64, BK=16, 256 threads.
// Raw fp32 bits fed to tf32 mma (HW truncation, RZ) — no cvt on load path.
#define TBM 128
#define TBN 64
#define TBK 16
#define TPAD 20

__global__ __launch_bounds__(256) void tf32_gemm_v4_kernel(
    const float* __restrict__ A, const float* __restrict__ W,
    const float* __restrict__ bias, float* __restrict__ C,
    int M, int N, int K)
{
    __shared__ unsigned As[TBM * TPAD];
    __shared__ unsigned Bs[TBN * TPAD];

    const int tid = threadIdx.x;
    const int wid = tid >> 5, lane = tid & 31;
    const int g = lane >> 2, t = lane & 3;
    const int wm = wid & 3, wn = wid >> 2;
    const int m0 = blockIdx.y * TBM;
    const int n0 = blockIdx.x * TBN;

    float acc[2][4][4];
#pragma unroll
    for (int mt = 0; mt < 2; mt++)
#pragma unroll
        for (int nt = 0; nt < 4; nt++)
#pragma unroll
            for (int i = 0; i < 4; i++) acc[mt][nt][i] = 0.f;

    // vector load mapping
    const int arow = tid >> 2;          // with j*64: rows 0..127 over 2 iters
    const int akq = (tid & 3) * 4;      // k column group
    const int brow = tid >> 2;          // 0..63
    const int bkq = (tid & 3) * 4;

    uint4 ra[2], rb;
    const int nk = K / TBK;

    // prefetch tile 0
#pragma unroll
    for (int j = 0; j < 2; j++)
        ra[j] = __ldg((const uint4*)&A[(size_t)(m0 + arow + j * 64) * K + akq]);
    rb = __ldg((const uint4*)&W[(size_t)(n0 + brow) * K + bkq]);

    for (int kt = 0; kt < nk; kt++) {
        // store current tile to smem (raw bits)
#pragma unroll
        for (int j = 0; j < 2; j++)
            *(uint4*)&As[(arow + j * 64) * TPAD + akq] = ra[j];
        *(uint4*)&Bs[brow * TPAD + bkq] = rb;
        __syncthreads();

        // prefetch next tile
        if (kt + 1 < nk) {
            const int kb = (kt + 1) * TBK;
#pragma unroll
            for (int j = 0; j < 2; j++)
                ra[j] = __ldg((const uint4*)&A[(size_t)(m0 + arow + j * 64) * K + kb + akq]);
            rb = __ldg((const uint4*)&W[(size_t)(n0 + brow) * K + kb + bkq]);
        }

        // compute: 2 k-steps of k=8
#pragma unroll
        for (int ks = 0; ks < 2; ks++) {
            const int k = ks * 8;
            unsigned af[2][4];
#pragma unroll
            for (int mt = 0; mt < 2; mt++) {
                int row = wm * 32 + mt * 16;
                af[mt][0] = As[(row + g) * TPAD + k + t];
                af[mt][1] = As[(row + g + 8) * TPAD + k + t];
                af[mt][2] = As[(row + g) * TPAD + k + t + 4];
                af[mt][3] = As[(row + g + 8) * TPAD + k + t + 4];
            }
#pragma unroll
            for (int nt = 0; nt < 4; nt++) {
                int col = wn * 32 + nt * 8;
                unsigned b0 = Bs[(col + g) * TPAD + k + t];
                unsigned b1 = Bs[(col + g) * TPAD + k + t + 4];
#pragma unroll
                for (int mt = 0; mt < 2; mt++) mma_tf32(acc[mt][nt], af[mt], b0, b1);
            }
        }
        __syncthreads();
    }

#pragma unroll
    for (int mt = 0; mt < 2; mt++) {
#pragma unroll
        for (int nt = 0; nt < 4; nt++) {
            int row = m0 + wm * 32 + mt * 16 + g;
            int col = n0 + wn * 32 + nt * 8 + 2 * t;
            float b0 = bias[col], b1 = bias[col + 1];
            C[(size_t)row * N + col]           = acc[mt][nt][0] + b0;
            C[(size_t)row * N + col + 1]       = acc[mt][nt][1] + b1;
            C[(size_t)(row + 8) * N + col]     = acc[mt][nt][2] + b0;
            C[(size_t)(row + 8) * N + col + 1] = acc[mt][nt][3] + b1;
        }
    }
}

// ================= TF32 GEMM, scalar guarded loads (any K, used for K=75) ==
__global__ __launch_bounds__(256) void tf32_gemm_bias_kernel(
    const float* __restrict__ A, const float* __restrict__ W,
    const float* __restrict__ bias, float* __restrict__ C,
    int M, int N, int K)
{
    __shared__ unsigned As[TBM * TPAD];
    __shared__ unsigned Bs[TBN * TPAD];

    const int tid = threadIdx.x;
    const int wid = tid >> 5, lane = tid & 31;
    const int g = lane >> 2, t = lane & 3;
    const int wm = wid & 3, wn = wid >> 2;
    const int m0 = blockIdx.y * TBM;
    const int n0 = blockIdx.x * TBN;

    float acc[2][4][4];
#pragma unroll
    for (int mt = 0; mt < 2; mt++)
#pragma unroll
        for (int nt = 0; nt < 4; nt++)
#pragma unroll
            for (int i = 0; i < 4; i++) acc[mt][nt][i] = 0.f;

    const int am = tid >> 4;
    const int ak = tid & 15;
    const int bn = tid >> 2;
    const int bk4 = (tid & 3) * 4;

    float ra[8], rb[4];
    const int nk = (K + TBK - 1) / TBK;

    {
#pragma unroll
        for (int i = 0; i < 8; i++) {
            int m = am + i * 16;
            ra[i] = (ak < K) ? __ldg(&A[(size_t)(m0 + m) * K + ak]) : 0.f;
        }
#pragma unroll
        for (int i = 0; i < 4; i++) {
            int k = bk4 + i;
            rb[i] = (k < K) ? __ldg(&W[(size_t)(n0 + bn) * K + k]) : 0.f;
        }
    }

    for (int kt = 0; kt < nk; kt++) {
#pragma unroll
        for (int i = 0; i < 8; i++) As[(am + i * 16) * TPAD + ak] = __float_as_uint(ra[i]);
#pragma unroll
        for (int i = 0; i < 4; i++) Bs[bn * TPAD + bk4 + i] = __float_as_uint(rb[i]);
        __syncthreads();

        if (kt + 1 < nk) {
            const int kb = (kt + 1) * TBK;
#pragma unroll
            for (int i = 0; i < 8; i++) {
                int m = am + i * 16;
                ra[i] = (kb + ak < K) ? __ldg(&A[(size_t)(m0 + m) * K + kb + ak]) : 0.f;
            }
#pragma unroll
            for (int i = 0; i < 4; i++) {
                int k = kb + bk4 + i;
                rb[i] = (k < K) ? __ldg(&W[(size_t)(n0 + bn) * K + k]) : 0.f;
            }
        }

#pragma unroll
        for (int ks = 0; ks < 2; ks++) {
            const int k = ks * 8;
            unsigned af[2][4];
#pragma unroll
            for (int mt = 0; mt < 2; mt++) {
                int row = wm * 32 + mt * 16;
                af[mt][0] = As[(row + g) * TPAD + k + t];
                af[mt][1] = As[(row + g + 8) * TPAD + k + t];
                af[mt][2] = As[(row + g) * TPAD + k + t + 4];
                af[mt][3] = As[(row + g + 8) * TPAD + k + t + 4];
            }
#pragma unroll
            for (int nt = 0; nt < 4; nt++) {
                int col = wn * 32 + nt * 8;
                unsigned b0 = Bs[(col + g) * TPAD + k + t];
                unsigned b1 = Bs[(col + g) * TPAD + k + t + 4];
#pragma unroll
                for (int mt = 0; mt < 2; mt++) mma_tf32(acc[mt][nt], af[mt], b0, b1);
            }
        }
        __syncthreads();
    }

#pragma unroll
    for (int mt = 0; mt < 2; mt++) {
#pragma unroll
        for (int nt = 0; nt < 4; nt++) {
            int row = m0 + wm * 32 + mt * 16 + g;
            int col = n0 + wn * 32 + nt * 8 + 2 * t;
            float b0 = bias[col], b1 = bias[col + 1];
            C[(size_t)row * N + col]           = acc[mt][nt][0] + b0;
            C[(size_t)row * N + col + 1]       = acc[mt][nt][1] + b1;
            C[(size_t)(row + 8) * N + col]     = acc[mt][nt][2] + b0;
            C[(size_t)(row + 8) * N + col + 1] = acc[mt][nt][3] + b1;
        }
    }
}

// ---------------- fp32 GEMM (tiny FC) --------------------------------------
#define GBM 128
#define GBN 64
#define GBK 8
__global__ __launch_bounds__(256) void gemm_bias_kernel(
    const float* __restrict__ A, const float* __restrict__ W,
    const float* __restrict__ bias, float* __restrict__ C,
    int M, int N, int K)
{
    __shared__ float As[GBK][GBM];
    __shared__ float Bs[GBK][GBN + 4];

    int tid = threadIdx.x;
    int tx = tid & 15;
    int ty = tid >> 4;
    int m0 = blockIdx.x * GBM;
    int n0 = blockIdx.y * GBN;

    float acc[8][4];
#pragma unroll
    for (int i = 0; i < 8; i++)
#pragma unroll
        for (int j = 0; j < 4; j++) acc[i][j] = 0.f;

    for (int k0 = 0; k0 < K; k0 += GBK) {
#pragma unroll
        for (int i = 0; i < 4; i++) {
            int idx = tid + i * 256;
            int m = idx >> 3, kk = idx & 7;
            float v = (k0 + kk < K) ? A[(size_t)(m0 + m) * K + k0 + kk] : 0.f;
            As[kk][m] = v;
        }
#pragma unroll
        for (int i = 0; i < 2; i++) {
            int idx = tid + i * 256;
            int n = idx >> 3, kk = idx & 7;
            float v = (k0 + kk < K) ? W[(size_t)(n0 + n) * K + k0 + kk] : 0.f;
            Bs[kk][n] = v;
        }
        __syncthreads();
#pragma unroll
        for (int kk = 0; kk < GBK; kk++) {
            float a[8], b[4];
#pragma unroll
            for (int i = 0; i < 8; i++) a[i] = As[kk][ty * 8 + i];
#pragma unroll
            for (int j = 0; j < 4; j++) b[j] = Bs[kk][tx * 4 + j];
#pragma unroll
            for (int i = 0; i < 8; i++)
#pragma unroll
                for (int j = 0; j < 4; j++) acc[i][j] = fmaf(a[i], b[j], acc[i][j]);
        }
        __syncthreads();
    }

    float bb[4];
#pragma unroll
    for (int j = 0; j < 4; j++) bb[j] = bias[n0 + tx * 4 + j];
#pragma unroll
    for (int i = 0; i < 8; i++) {
        size_t row = (size_t)(m0 + ty * 8 + i) * N + n0 + tx * 4;
#pragma unroll
        for (int j = 0; j < 4; j++) C[row + j] = acc[i][j] + bb[j];
    }
}

// ---------------- cluster-based persistent GRU recurrence (R4, proven) -----
// 16 clusters x 8 CTAs. Cluster = 16 batches; CTA rank = 32 units (96 gate
// rows). W_hh fragments register-resident. Per step: mma on local smem h
// (double-buffered), epilogue pushes new h slice to all 8 cluster CTAs via
// st.shared::cluster, one cluster.sync per step.
#define CL 8
#define RT_THREADS 192
#define RT_GRID 128
#define HP 260          // hs_tf row stride (words): banks 4g+t -> conflict-free
#define DSP 17          // Ds row stride
#define H32P 33         // hs32 row stride

__device__ __forceinline__ unsigned mapa_rank(unsigned addr, unsigned rank) {
    unsigned r;
    asm("mapa.shared::cluster.u32 %0, %1, %2;" : "=r"(r) : "r"(addr), "r"(rank));
    return r;
}

__global__ __launch_bounds__(RT_THREADS, 1) __cluster_dims__(CL, 1, 1)
void gru_rec_cluster_kernel(
    const float* __restrict__ W_hh, const float* __restrict__ b_hh, int layer0)
{
    __shared__ unsigned hs_tf[2][16 * HP];   // h (tf32 bits) [b][unit], ping-pong
    __shared__ float    hs32[2][16 * H32P];  // own 32 units, exact fp32, ping-pong
    __shared__ float    Ds[96 * DSP];        // mma accums [gate-row][b]

    const int tid = threadIdx.x;
    const int wid = tid >> 5;             // 0..5
    const int lane = tid & 31;
    const int g = lane >> 2, t = lane & 3;

    unsigned rank;
    asm("mov.u32 %0, %%cluster_ctarank;" : "=r"(rank));
    const int bg = blockIdx.x >> 3;       // cluster id -> batch group 0..15
    const int j0 = (int)rank * 32;        // this CTA's unit base
    const int b0 = bg * 16;

    // ---- preload static A fragments (W_hh slice) into registers ----
    const int gate_w = wid >> 1;
    const int wrow = gate_w * HH + j0 + (wid & 1) * 16;
    unsigned a[32][4];
#pragma unroll
    for (int ks = 0; ks < 32; ks++) {
        int k = ks * 8;
        a[ks][0] = f2tf32(__ldg(&W_hh[(size_t)(wrow + g) * HH + k + t]));
        a[ks][1] = f2tf32(__ldg(&W_hh[(size_t)(wrow + g + 8) * HH + k + t]));
        a[ks][2] = f2tf32(__ldg(&W_hh[(size_t)(wrow + g) * HH + k + t + 4]));
        a[ks][3] = f2tf32(__ldg(&W_hh[(size_t)(wrow + g + 8) * HH + k + t + 4]));
    }

    // ---- epilogue assignment: thread (eb, ju4) owns units ju4*4..+3, batch eb
    const int eb = (tid & 127) >> 3;      // 0..15
    const int ju4 = tid & 7;              // 0..7
    float bhr[4], bhz[4], bhn[4];
    if (tid < 128) {
#pragma unroll
        for (int i = 0; i < 4; i++) {
            int j = j0 + ju4 * 4 + i;
            bhr[i] = __ldg(&b_hh[j]);
            bhz[i] = __ldg(&b_hh[HH + j]);
            bhn[i] = __ldg(&b_hh[2 * HH + j]);
        }
    }

    // precompute cluster-mapped destination addresses for the h push
    unsigned dst[CL];
    unsigned buf_delta = 0;
    {
        unsigned l0 = smem_u32(&hs_tf[0][eb * HP + j0 + ju4 * 4]);
        unsigned l1 = smem_u32(&hs_tf[1][eb * HP + j0 + ju4 * 4]);
        buf_delta = l1 - l0;
#pragma unroll
        for (int r = 0; r < CL; r++) dst[r] = mapa_rank(l0, (unsigned)r);
    }

    // ---- init: zero both h buffers ----
    for (int idx = tid; idx < 16 * HP; idx += RT_THREADS) {
        hs_tf[0][idx] = 0u;
        hs_tf[1][idx] = 0u;
    }
    for (int idx = tid; idx < 16 * H32P; idx += RT_THREADS) {
        hs32[0][idx] = 0.f;
        hs32[1][idx] = 0.f;
    }
    __syncthreads();
    CLUSTER_SYNC();

    for (int s = 0; s < TT; s++) {
        const int cur = s & 1;
        const int nxt = cur ^ 1;

        // ---- xg prefetch (issued before mma; DRAM latency hides under mma) ----
        float4 xr4, xz4, xn4;
        if (tid < 128) {
            const float* xgp = &g_xg[((size_t)(b0 + eb) * TT + s) * G3 + j0 + ju4 * 4];
            xr4 = __ldcg((const float4*)&xgp[0]);
            xz4 = __ldcg((const float4*)&xgp[HH]);
            xn4 = __ldcg((const float4*)&xgp[2 * HH]);
        }

        // ---- tensor-core matmul: D[96 x 16] = W_slice @ h^T ----
        const unsigned* hb = hs_tf[cur];
        float c0[4] = {0.f, 0.f, 0.f, 0.f};
        float c1[4] = {0.f, 0.f, 0.f, 0.f};
#pragma unroll
        for (int ks = 0; ks < 32; ks++) {
            int k = ks * 8;
            unsigned b00 = hb[g * HP + k + t];
            unsigned b01 = hb[g * HP + k + t + 4];
            unsigned b10 = hb[(8 + g) * HP + k + t];
            unsigned b11 = hb[(8 + g) * HP + k + t + 4];
            mma_tf32(c0, a[ks], b00, b01);
            mma_tf32(c1, a[ks], b10, b11);
        }
        {
            int lr = wid * 16 + g;
            Ds[lr * DSP + 2 * t]           = c0[0];
            Ds[lr * DSP + 2 * t + 1]       = c0[1];
            Ds[(lr + 8) * DSP + 2 * t]     = c0[2];
            Ds[(lr + 8) * DSP + 2 * t + 1] = c0[3];
            Ds[lr * DSP + 8 + 2 * t]           = c1[0];
            Ds[lr * DSP + 8 + 2 * t + 1]       = c1[1];
            Ds[(lr + 8) * DSP + 8 + 2 * t]     = c1[2];
            Ds[(lr + 8) * DSP + 8 + 2 * t + 1] = c1[3];
        }
        __syncthreads();

        // ---- gates + state update + cluster-wide h push ----
        if (tid < 128) {
            float hnew[4];
#pragma unroll
            for (int i = 0; i < 4; i++) {
                int jl = ju4 * 4 + i;
                float xr = (i == 0) ? xr4.x : (i == 1) ? xr4.y : (i == 2) ? xr4.z : xr4.w;
                float xz = (i == 0) ? xz4.x : (i == 1) ? xz4.y : (i == 2) ? xz4.z : xz4.w;
                float xn = (i == 0) ? xn4.x : (i == 1) ? xn4.y : (i == 2) ? xn4.z : xn4.w;
                float pr = Ds[jl * DSP + eb];
                float pz = Ds[(32 + jl) * DSP + eb];
                float pn = Ds[(64 + jl) * DSP + eb];
                float hp = hs32[cur][eb * H32P + jl];
                float r = 1.f / (1.f + expf(-(xr + bhr[i] + pr)));
                float z = 1.f / (1.f + expf(-(xz + bhz[i] + pz)));
                float nn = tanhf(xn + r * (bhn[i] + pn));
                hnew[i] = (1.f - z) * nn + z * hp;
            }
#pragma unroll
            for (int i = 0; i < 4; i++)
                hs32[nxt][eb * H32P + ju4 * 4 + i] = hnew[i];
            unsigned u0 = f2tf32(hnew[0]), u1 = f2tf32(hnew[1]);
            unsigned u2 = f2tf32(hnew[2]), u3 = f2tf32(hnew[3]);
            unsigned bofs = (nxt ? buf_delta : 0u);
#pragma unroll
            for (int r = 0; r < CL; r++) {
                asm volatile("st.shared::cluster.v4.b32 [%0], {%1,%2,%3,%4};"
                             :: "r"(dst[r] + bofs), "r"(u0), "r"(u1), "r"(u2), "r"(u3)
                             : "memory");
            }
            if (layer0) {
                float4 hv = make_float4(hnew[0], hnew[1], hnew[2], hnew[3]);
                *(float4*)&g_out0[((size_t)(b0 + eb) * TT + s) * HH + j0 + ju4 * 4] = hv;
            } else if (s == TT - 1) {
                float4 hv = make_float4(hnew[0], hnew[1], hnew[2], hnew[3]);
                *(float4*)&g_hT[(size_t)(b0 + eb) * HH + j0 + ju4 * 4] = hv;
            }
        }

        // ---- one cluster barrier per step (release/acquire covers DSMEM) ----
        CLUSTER_SYNC();
    }
}

// ---------------------------------------------------------------------------
extern "C" void kernel_launch(void* const* d_in, const int* in_sizes, int n_in,
                              void* d_out, int out_size)
{
    const float* x     = (const float*)d_in[0];
    const float* W_ih0 = (const float*)d_in[1];
    const float* W_hh0 = (const float*)d_in[2];
    const float* b_ih0 = (const float*)d_in[3];
    const float* b_hh0 = (const float*)d_in[4];
    const float* W_ih1 = (const float*)d_in[5];
    const float* W_hh1 = (const float*)d_in[6];
    const float* b_ih1 = (const float*)d_in[7];
    const float* b_hh1 = (const float*)d_in[8];
    const float* fc_W  = (const float*)d_in[9];
    const float* fc_b  = (const float*)d_in[10];
    float* out = (float*)d_out;

    float *xg, *out0, *hT;
    cudaGetSymbolAddress((void**)&xg,   g_xg);
    cudaGetSymbolAddress((void**)&out0, g_out0);
    cudaGetSymbolAddress((void**)&hT,   g_hT);

    // layer 0 input preactivations: [BT,75] @ [768,75]^T (scalar-load tf32 GEMM)
    tf32_gemm_bias_kernel<<<dim3(G3 / TBN, BT / TBM), 256>>>(x, W_ih0, b_ih0, xg, BT, G3, INDIM);
    // layer 0 recurrence -> g_out0 (cluster + DSMEM, R4-proven)
    gru_rec_cluster_kernel<<<RT_GRID, RT_THREADS>>>(W_hh0, b_hh0, 1);
    // layer 1 input preactivations: [BT,256] @ [768,256]^T (vector-load tf32 GEMM)
    tf32_gemm_v4_kernel<<<dim3(G3 / TBN, BT / TBM), 256>>>(out0, W_ih1, b_ih1, xg, BT, G3, HH);
    // layer 1 recurrence -> g_hT
    gru_rec_cluster_kernel<<<RT_GRID, RT_THREADS>>>(W_hh1, b_hh1, 0);
    // FC: [256,256] @ [256,256]^T + b (fp32, tiny)
    gemm_bias_kernel<<<dim3(BB / GBM, HH / GBN), 256>>>(hT, fc_W, fc_b, out, BB, HH, HH);
}

// round 8
// speedup vs baseline: 2.3480x; 1.7784x over previous
#include <cuda_runtime.h>
#include <cuda_fp16.h>
#include <math.h>

// Problem dims
#define BB 256
#define TT 512
#define HH 256
#define G3 768          // 3*H
#define INDIM 75
#define BT (BB*TT)      // 131072

// ---------------- scratch (device globals; no allocations allowed) ---------
__device__ float g_xg[(size_t)BB * TT * G3];     // input-gate preactivations (reused per layer)
__device__ float g_out0[(size_t)BB * TT * HH];   // layer-0 hidden states
__device__ float g_hT[BB * HH];                  // layer-1 final hidden state

__device__ __forceinline__ unsigned f2tf32(float v) {
    unsigned u;
    asm("cvt.rna.tf32.f32 %0, %1;" : "=r"(u) : "f"(v));
    return u;
}

__device__ __forceinline__ unsigned pack_h2(float x, float y) {
    __half2 h = __floats2half2_rn(x, y);
    return *(unsigned*)&h;
}

__device__ __forceinline__ void mma_tf32(float c[4], const unsigned a[4], unsigned b0, unsigned b1) {
    asm volatile(
        "mma.sync.aligned.m16n8k8.row.col.f32.tf32.tf32.f32 "
        "{%0,%1,%2,%3}, {%4,%5,%6,%7}, {%8,%9}, {%0,%1,%2,%3};"
        : "+f"(c[0]), "+f"(c[1]), "+f"(c[2]), "+f"(c[3])
        : "r"(a[0]), "r"(a[1]), "r"(a[2]), "r"(a[3]), "r"(b0), "r"(b1));
}

__device__ __forceinline__ void mma_f16(float c[4], const unsigned a[4], unsigned b0, unsigned b1) {
    asm volatile(
        "mma.sync.aligned.m16n8k16.row.col.f32.f16.f16.f32 "
        "{%0,%1,%2,%3}, {%4,%5,%6,%7}, {%8,%9}, {%0,%1,%2,%3};"
        : "+f"(c[0]), "+f"(c[1]), "+f"(c[2]), "+f"(c[3])
        : "r"(a[0]), "r"(a[1]), "r"(a[2]), "r"(a[3]), "r"(b0), "r"(b1));
}

__device__ __forceinline__ unsigned smem_u32(const void* p) {
    unsigned a;
    asm("{ .reg .u64 t; cvta.to.shared.u64 t, %1; cvt.u32.u64 %0, t; }" : "=r"(a) : "l"(p));
    return a;
}

__device__ __forceinline__ unsigned mapa_rank(unsigned addr, unsigned rank) {
    unsigned r;
    asm("mapa.shared::cluster.u32 %0, %1, %2;" : "=r"(r) : "r"(addr), "r"(rank));
    return r;
}

#define CLUSTER_SYNC() do {                                            \
    asm volatile("barrier.cluster.arrive.aligned;" ::: "memory");      \
    asm volatile("barrier.cluster.wait.aligned;" ::: "memory");        \
} while (0)

// ================= TF32 GEMM, vector loads + RNA convert (K=256) ===========
#define TBM 128
#define TBN 64
#define TBK 16
#define TPAD 20

__global__ __launch_bounds__(256) void tf32_gemm_v4_kernel(
    const float* __restrict__ A, const float* __restrict__ W,
    const float* __restrict__ bias, float* __restrict__ C,
    int M, int N, int K)
{
    __shared__ unsigned As[TBM * TPAD];
    __shared__ unsigned Bs[TBN * TPAD];

    const int tid = threadIdx.x;
    const int wid = tid >> 5, lane = tid & 31;
    const int g = lane >> 2, t = lane & 3;
    const int wm = wid & 3, wn = wid >> 2;
    const int m0 = blockIdx.y * TBM;
    const int n0 = blockIdx.x * TBN;

    float acc[2][4][4];
#pragma unroll
    for (int mt = 0; mt < 2; mt++)
#pragma unroll
        for (int nt = 0; nt < 4; nt++)
#pragma unroll
            for (int i = 0; i < 4; i++) acc[mt][nt][i] = 0.f;

    const int arow = tid >> 2;
    const int akq = (tid & 3) * 4;
    const int brow = tid >> 2;
    const int bkq = (tid & 3) * 4;

    float4 ra[2], rb;
    const int nk = K / TBK;

#pragma unroll
    for (int j = 0; j < 2; j++)
        ra[j] = __ldg((const float4*)&A[(size_t)(m0 + arow + j * 64) * K + akq]);
    rb = __ldg((const float4*)&W[(size_t)(n0 + brow) * K + bkq]);

    for (int kt = 0; kt < nk; kt++) {
#pragma unroll
        for (int j = 0; j < 2; j++) {
            uint4 u;
            u.x = f2tf32(ra[j].x); u.y = f2tf32(ra[j].y);
            u.z = f2tf32(ra[j].z); u.w = f2tf32(ra[j].w);
            *(uint4*)&As[(arow + j * 64) * TPAD + akq] = u;
        }
        {
            uint4 u;
            u.x = f2tf32(rb.x); u.y = f2tf32(rb.y);
            u.z = f2tf32(rb.z); u.w = f2tf32(rb.w);
            *(uint4*)&Bs[brow * TPAD + bkq] = u;
        }
        __syncthreads();

        if (kt + 1 < nk) {
            const int kb = (kt + 1) * TBK;
#pragma unroll
            for (int j = 0; j < 2; j++)
                ra[j] = __ldg((const float4*)&A[(size_t)(m0 + arow + j * 64) * K + kb + akq]);
            rb = __ldg((const float4*)&W[(size_t)(n0 + brow) * K + kb + bkq]);
        }

#pragma unroll
        for (int ks = 0; ks < 2; ks++) {
            const int k = ks * 8;
            unsigned af[2][4];
#pragma unroll
            for (int mt = 0; mt < 2; mt++) {
                int row = wm * 32 + mt * 16;
                af[mt][0] = As[(row + g) * TPAD + k + t];
                af[mt][1] = As[(row + g + 8) * TPAD + k + t];
                af[mt][2] = As[(row + g) * TPAD + k + t + 4];
                af[mt][3] = As[(row + g + 8) * TPAD + k + t + 4];
            }
#pragma unroll
            for (int nt = 0; nt < 4; nt++) {
                int col = wn * 32 + nt * 8;
                unsigned b0 = Bs[(col + g) * TPAD + k + t];
                unsigned b1 = Bs[(col + g) * TPAD + k + t + 4];
#pragma unroll
                for (int mt = 0; mt < 2; mt++) mma_tf32(acc[mt][nt], af[mt], b0, b1);
            }
        }
        __syncthreads();
    }

#pragma unroll
    for (int mt = 0; mt < 2; mt++) {
#pragma unroll
        for (int nt = 0; nt < 4; nt++) {
            int row = m0 + wm * 32 + mt * 16 + g;
            int col = n0 + wn * 32 + nt * 8 + 2 * t;
            float b0 = bias[col], b1 = bias[col + 1];
            C[(size_t)row * N + col]           = acc[mt][nt][0] + b0;
            C[(size_t)row * N + col + 1]       = acc[mt][nt][1] + b1;
            C[(size_t)(row + 8) * N + col]     = acc[mt][nt][2] + b0;
            C[(size_t)(row + 8) * N + col + 1] = acc[mt][nt][3] + b1;
        }
    }
}

// ================= TF32 GEMM, scalar guarded loads + RNA (K=75) ============
__global__ __launch_bounds__(256) void tf32_gemm_bias_kernel(
    const float* __restrict__ A, const float* __restrict__ W,
    const float* __restrict__ bias, float* __restrict__ C,
    int M, int N, int K)
{
    __shared__ unsigned As[TBM * TPAD];
    __shared__ unsigned Bs[TBN * TPAD];

    const int tid = threadIdx.x;
    const int wid = tid >> 5, lane = tid & 31;
    const int g = lane >> 2, t = lane & 3;
    const int wm = wid & 3, wn = wid >> 2;
    const int m0 = blockIdx.y * TBM;
    const int n0 = blockIdx.x * TBN;

    float acc[2][4][4];
#pragma unroll
    for (int mt = 0; mt < 2; mt++)
#pragma unroll
        for (int nt = 0; nt < 4; nt++)
#pragma unroll
            for (int i = 0; i < 4; i++) acc[mt][nt][i] = 0.f;

    const int am = tid >> 4;
    const int ak = tid & 15;
    const int bn = tid >> 2;
    const int bk4 = (tid & 3) * 4;

    float ra[8], rb[4];
    const int nk = (K + TBK - 1) / TBK;

    {
#pragma unroll
        for (int i = 0; i < 8; i++) {
            int m = am + i * 16;
            ra[i] = (ak < K) ? __ldg(&A[(size_t)(m0 + m) * K + ak]) : 0.f;
        }
#pragma unroll
        for (int i = 0; i < 4; i++) {
            int k = bk4 + i;
            rb[i] = (k < K) ? __ldg(&W[(size_t)(n0 + bn) * K + k]) : 0.f;
        }
    }

    for (int kt = 0; kt < nk; kt++) {
#pragma unroll
        for (int i = 0; i < 8; i++) As[(am + i * 16) * TPAD + ak] = f2tf32(ra[i]);
#pragma unroll
        for (int i = 0; i < 4; i++) Bs[bn * TPAD + bk4 + i] = f2tf32(rb[i]);
        __syncthreads();

        if (kt + 1 < nk) {
            const int kb = (kt + 1) * TBK;
#pragma unroll
            for (int i = 0; i < 8; i++) {
                int m = am + i * 16;
                ra[i] = (kb + ak < K) ? __ldg(&A[(size_t)(m0 + m) * K + kb + ak]) : 0.f;
            }
#pragma unroll
            for (int i = 0; i < 4; i++) {
                int k = kb + bk4 + i;
                rb[i] = (k < K) ? __ldg(&W[(size_t)(n0 + bn) * K + k]) : 0.f;
            }
        }

#pragma unroll
        for (int ks = 0; ks < 2; ks++) {
            const int k = ks * 8;
            unsigned af[2][4];
#pragma unroll
            for (int mt = 0; mt < 2; mt++) {
                int row = wm * 32 + mt * 16;
                af[mt][0] = As[(row + g) * TPAD + k + t];
                af[mt][1] = As[(row + g + 8) * TPAD + k + t];
                af[mt][2] = As[(row + g) * TPAD + k + t + 4];
                af[mt][3] = As[(row + g + 8) * TPAD + k + t + 4];
            }
#pragma unroll
            for (int nt = 0; nt < 4; nt++) {
                int col = wn * 32 + nt * 8;
                unsigned b0 = Bs[(col + g) * TPAD + k + t];
                unsigned b1 = Bs[(col + g) * TPAD + k + t + 4];
#pragma unroll
                for (int mt = 0; mt < 2; mt++) mma_tf32(acc[mt][nt], af[mt], b0, b1);
            }
        }
        __syncthreads();
    }

#pragma unroll
    for (int mt = 0; mt < 2; mt++) {
#pragma unroll
        for (int nt = 0; nt < 4; nt++) {
            int row = m0 + wm * 32 + mt * 16 + g;
            int col = n0 + wn * 32 + nt * 8 + 2 * t;
            float b0 = bias[col], b1 = bias[col + 1];
            C[(size_t)row * N + col]           = acc[mt][nt][0] + b0;
            C[(size_t)row * N + col + 1]       = acc[mt][nt][1] + b1;
            C[(size_t)(row + 8) * N + col]     = acc[mt][nt][2] + b0;
            C[(size_t)(row + 8) * N + col + 1] = acc[mt][nt][3] + b1;
        }
    }
}

// ---------------- fp32 GEMM (tiny FC) --------------------------------------
#define GBM 128
#define GBN 64
#define GBK 8
__global__ __launch_bounds__(256) void gemm_bias_kernel(
    const float* __restrict__ A, const float* __restrict__ W,
    const float* __restrict__ bias, float* __restrict__ C,
    int M, int N, int K)
{
    __shared__ float As[GBK][GBM];
    __shared__ float Bs[GBK][GBN + 4];

    int tid = threadIdx.x;
    int tx = tid & 15;
    int ty = tid >> 4;
    int m0 = blockIdx.x * GBM;
    int n0 = blockIdx.y * GBN;

    float acc[8][4];
#pragma unroll
    for (int i = 0; i < 8; i++)
#pragma unroll
        for (int j = 0; j < 4; j++) acc[i][j] = 0.f;

    for (int k0 = 0; k0 < K; k0 += GBK) {
#pragma unroll
        for (int i = 0; i < 4; i++) {
            int idx = tid + i * 256;
            int m = idx >> 3, kk = idx & 7;
            float v = (k0 + kk < K) ? A[(size_t)(m0 + m) * K + k0 + kk] : 0.f;
            As[kk][m] = v;
        }
#pragma unroll
        for (int i = 0; i < 2; i++) {
            int idx = tid + i * 256;
            int n = idx >> 3, kk = idx & 7;
            float v = (k0 + kk < K) ? W[(size_t)(n0 + n) * K + k0 + kk] : 0.f;
            Bs[kk][n] = v;
        }
        __syncthreads();
#pragma unroll
        for (int kk = 0; kk < GBK; kk++) {
            float a[8], b[4];
#pragma unroll
            for (int i = 0; i < 8; i++) a[i] = As[kk][ty * 8 + i];
#pragma unroll
            for (int j = 0; j < 4; j++) b[j] = Bs[kk][tx * 4 + j];
#pragma unroll
            for (int i = 0; i < 8; i++)
#pragma unroll
                for (int j = 0; j < 4; j++) acc[i][j] = fmaf(a[i], b[j], acc[i][j]);
        }
        __syncthreads();
    }

    float bb[4];
#pragma unroll
    for (int j = 0; j < 4; j++) bb[j] = bias[n0 + tx * 4 + j];
#pragma unroll
    for (int i = 0; i < 8; i++) {
        size_t row = (size_t)(m0 + ty * 8 + i) * N + n0 + tx * 4;
#pragma unroll
        for (int j = 0; j < 4; j++) C[row + j] = acc[i][j] + bb[j];
    }
}

// ---------------- cluster GRU recurrence, fp16 mma -------------------------
// 16 clusters x 8 CTAs; CTA = 32 units (96 gate rows) x 16 batches.
// fp16 m16n8k16 (11 mantissa bits = tf32 precision; h in (-1,1), W ~ 1/16).
// W_hh fragments register-resident (64 regs). h exchanged as fp16 (8 KB/step
// DSMEM push, half of tf32). Exact fp32 h_prev carried in smem for z*h chain.
#define CL 8
#define RT_THREADS 192
#define RT_GRID 128
#define HPW 132         // h row stride in 32-bit words: banks 4g+t conflict-free
#define DSP 17          // Ds row stride
#define H32P 33         // hs32 row stride

__global__ __launch_bounds__(RT_THREADS, 1) __cluster_dims__(CL, 1, 1)
void gru_rec_cluster_kernel(
    const float* __restrict__ W_hh, const float* __restrict__ b_hh, int layer0)
{
    __shared__ unsigned hs16[2][16 * HPW];   // h (fp16x2) [b][k-pair], ping-pong
    __shared__ float    hs32[2][16 * H32P];  // own 32 units, exact fp32, ping-pong
    __shared__ float    Ds[96 * DSP];        // mma accums [gate-row][b]

    const int tid = threadIdx.x;
    const int wid = tid >> 5;             // 0..5
    const int lane = tid & 31;
    const int g = lane >> 2, t = lane & 3;

    unsigned rank;
    asm("mov.u32 %0, %%cluster_ctarank;" : "=r"(rank));
    const int bg = blockIdx.x >> 3;       // batch group 0..15
    const int j0 = (int)rank * 32;        // this CTA's unit base
    const int b0 = bg * 16;

    // ---- preload static A fragments (W_hh slice, fp16) into registers ----
    // warp wid owns gate rows [wrow, wrow+16)
    const int gate_w = wid >> 1;
    const int wrow = gate_w * HH + j0 + (wid & 1) * 16;
    unsigned a[16][4];
#pragma unroll
    for (int ks = 0; ks < 16; ks++) {
        int k = ks * 16;
        const float* r0 = &W_hh[(size_t)(wrow + g) * HH + k];
        const float* r1 = &W_hh[(size_t)(wrow + g + 8) * HH + k];
        a[ks][0] = pack_h2(__ldg(&r0[2 * t]),     __ldg(&r0[2 * t + 1]));
        a[ks][1] = pack_h2(__ldg(&r1[2 * t]),     __ldg(&r1[2 * t + 1]));
        a[ks][2] = pack_h2(__ldg(&r0[2 * t + 8]), __ldg(&r0[2 * t + 9]));
        a[ks][3] = pack_h2(__ldg(&r1[2 * t + 8]), __ldg(&r1[2 * t + 9]));
    }

    // ---- epilogue assignment: thread (eb, ju4) owns units ju4*4..+3, batch eb
    const int eb = (tid & 127) >> 3;      // 0..15
    const int ju4 = tid & 7;              // 0..7
    float bhr[4], bhz[4], bhn[4];
    if (tid < 128) {
#pragma unroll
        for (int i = 0; i < 4; i++) {
            int j = j0 + ju4 * 4 + i;
            bhr[i] = __ldg(&b_hh[j]);
            bhz[i] = __ldg(&b_hh[HH + j]);
            bhn[i] = __ldg(&b_hh[2 * HH + j]);
        }
    }

    // cluster-mapped destinations for the h push (word offset = j/2)
    unsigned dst[CL];
    unsigned buf_delta = 0;
    {
        unsigned l0 = smem_u32(&hs16[0][eb * HPW + (j0 >> 1) + ju4 * 2]);
        unsigned l1 = smem_u32(&hs16[1][eb * HPW + (j0 >> 1) + ju4 * 2]);
        buf_delta = l1 - l0;
#pragma unroll
        for (int r = 0; r < CL; r++) dst[r] = mapa_rank(l0, (unsigned)r);
    }

    // ---- init: zero both h buffers ----
    for (int idx = tid; idx < 16 * HPW; idx += RT_THREADS) {
        hs16[0][idx] = 0u;
        hs16[1][idx] = 0u;
    }
    for (int idx = tid; idx < 16 * H32P; idx += RT_THREADS) {
        hs32[0][idx] = 0.f;
        hs32[1][idx] = 0.f;
    }
    __syncthreads();
    CLUSTER_SYNC();

    for (int s = 0; s < TT; s++) {
        const int cur = s & 1;
        const int nxt = cur ^ 1;

        // ---- xg prefetch (hidden under mma) ----
        float4 xr4, xz4, xn4;
        if (tid < 128) {
            const float* xgp = &g_xg[((size_t)(b0 + eb) * TT + s) * G3 + j0 + ju4 * 4];
            xr4 = __ldcg((const float4*)&xgp[0]);
            xz4 = __ldcg((const float4*)&xgp[HH]);
            xn4 = __ldcg((const float4*)&xgp[2 * HH]);
        }

        // ---- fp16 tensor-core matmul: D[96 x 16] = W_slice @ h^T ----
        const unsigned* hb = hs16[cur];
        float c0[4] = {0.f, 0.f, 0.f, 0.f};   // batches 0..7
        float c1[4] = {0.f, 0.f, 0.f, 0.f};   // batches 8..15
#pragma unroll
        for (int ks = 0; ks < 16; ks++) {
            int w = ks * 8;    // word base for this k-step
            unsigned b00 = hb[g * HPW + w + t];
            unsigned b01 = hb[g * HPW + w + t + 4];
            unsigned b10 = hb[(8 + g) * HPW + w + t];
            unsigned b11 = hb[(8 + g) * HPW + w + t + 4];
            mma_f16(c0, a[ks], b00, b01);
            mma_f16(c1, a[ks], b10, b11);
        }
        {
            int lr = wid * 16 + g;
            Ds[lr * DSP + 2 * t]           = c0[0];
            Ds[lr * DSP + 2 * t + 1]       = c0[1];
            Ds[(lr + 8) * DSP + 2 * t]     = c0[2];
            Ds[(lr + 8) * DSP + 2 * t + 1] = c0[3];
            Ds[lr * DSP + 8 + 2 * t]           = c1[0];
            Ds[lr * DSP + 8 + 2 * t + 1]       = c1[1];
            Ds[(lr + 8) * DSP + 8 + 2 * t]     = c1[2];
            Ds[(lr + 8) * DSP + 8 + 2 * t + 1] = c1[3];
        }
        __syncthreads();

        // ---- gates + state update + cluster-wide h push (fp16) ----
        if (tid < 128) {
            float hnew[4];
#pragma unroll
            for (int i = 0; i < 4; i++) {
                int jl = ju4 * 4 + i;
                float xr = (i == 0) ? xr4.x : (i == 1) ? xr4.y : (i == 2) ? xr4.z : xr4.w;
                float xz = (i == 0) ? xz4.x : (i == 1) ? xz4.y : (i == 2) ? xz4.z : xz4.w;
                float xn = (i == 0) ? xn4.x : (i == 1) ? xn4.y : (i == 2) ? xn4.z : xn4.w;
                float pr = Ds[jl * DSP + eb];
                float pz = Ds[(32 + jl) * DSP + eb];
                float pn = Ds[(64 + jl) * DSP + eb];
                float hp = hs32[cur][eb * H32P + jl];
                float r = 1.f / (1.f + expf(-(xr + bhr[i] + pr)));
                float z = 1.f / (1.f + expf(-(xz + bhz[i] + pz)));
                float nn = tanhf(xn + r * (bhn[i] + pn));
                hnew[i] = (1.f - z) * nn + z * hp;
            }
#pragma unroll
            for (int i = 0; i < 4; i++)
                hs32[nxt][eb * H32P + ju4 * 4 + i] = hnew[i];
            unsigned u0 = pack_h2(hnew[0], hnew[1]);
            unsigned u1 = pack_h2(hnew[2], hnew[3]);
            unsigned bofs = (nxt ? buf_delta : 0u);
#pragma unroll
            for (int r = 0; r < CL; r++) {
                asm volatile("st.shared::cluster.v2.b32 [%0], {%1,%2};"
                             :: "r"(dst[r] + bofs), "r"(u0), "r"(u1)
                             : "memory");
            }
            if (layer0) {
                float4 hv = make_float4(hnew[0], hnew[1], hnew[2], hnew[3]);
                *(float4*)&g_out0[((size_t)(b0 + eb) * TT + s) * HH + j0 + ju4 * 4] = hv;
            } else if (s == TT - 1) {
                float4 hv = make_float4(hnew[0], hnew[1], hnew[2], hnew[3]);
                *(float4*)&g_hT[(size_t)(b0 + eb) * HH + j0 + ju4 * 4] = hv;
            }
        }

        // ---- one cluster barrier per step (release/acquire covers DSMEM) ----
        CLUSTER_SYNC();
    }
}

// ---------------------------------------------------------------------------
extern "C" void kernel_launch(void* const* d_in, const int* in_sizes, int n_in,
                              void* d_out, int out_size)
{
    const float* x     = (const float*)d_in[0];
    const float* W_ih0 = (const float*)d_in[1];
    const float* W_hh0 = (const float*)d_in[2];
    const float* b_ih0 = (const float*)d_in[3];
    const float* b_hh0 = (const float*)d_in[4];
    const float* W_ih1 = (const float*)d_in[5];
    const float* W_hh1 = (const float*)d_in[6];
    const float* b_ih1 = (const float*)d_in[7];
    const float* b_hh1 = (const float*)d_in[8];
    const float* fc_W  = (const float*)d_in[9];
    const float* fc_b  = (const float*)d_in[10];
    float* out = (float*)d_out;

    float *xg, *out0, *hT;
    cudaGetSymbolAddress((void**)&xg,   g_xg);
    cudaGetSymbolAddress((void**)&out0, g_out0);
    cudaGetSymbolAddress((void**)&hT,   g_hT);

    // layer 0 input preactivations: [BT,75] @ [768,75]^T (scalar tf32 GEMM, RNA)
    tf32_gemm_bias_kernel<<<dim3(G3 / TBN, BT / TBM), 256>>>(x, W_ih0, b_ih0, xg, BT, G3, INDIM);
    // layer 0 recurrence -> g_out0 (cluster + DSMEM, fp16 mma)
    gru_rec_cluster_kernel<<<RT_GRID, RT_THREADS>>>(W_hh0, b_hh0, 1);
    // layer 1 input preactivations: [BT,256] @ [768,256]^T (v4 tf32 GEMM, RNA)
    tf32_gemm_v4_kernel<<<dim3(G3 / TBN, BT / TBM), 256>>>(out0, W_ih1, b_ih1, xg, BT, G3, HH);
    // layer 1 recurrence -> g_hT
    gru_rec_cluster_kernel<<<RT_GRID, RT_THREADS>>>(W_hh1, b_hh1, 0);
    // FC: [256,256] @ [256,256]^T + b (fp32, tiny)
    gemm_bias_kernel<<<dim3(BB / GBM, HH / GBN), 256>>>(hT, fc_W, fc_b, out, BB, HH, HH);
}